// round 1
// baseline (speedup 1.0000x reference)
#include <cuda_runtime.h>
#include <math.h>

#define NN 8192
#define D 128
#define WORDS (NN/32)       // 256 mask words per row
#define R 16                // rows per attention CTA
#define CK 128              // j-chunk
#define NEG_INF -9e15f
#define ATT_SMEM ((CK*D + R*CK)*4)

// ---------------- device scratch (no allocs allowed) ----------------
__device__ unsigned int g_bits[NN*WORDS];   // 8 MB packed adjacency
__device__ float g_Wh[2*NN*D];              // Wh per head
__device__ float g_f1[2*NN];
__device__ float g_f2[2*NN];
__device__ float g_h[NN*256];               // concat(elu(head0), elu(head1))
__device__ float g_Wh2[NN*D];
__device__ float g_f1o[NN];
__device__ float g_f2o[NN];
__device__ float g_comb[NN*256];
__device__ float g_mlp1[NN*256];
__device__ float g_mlp2[NN*D];
__device__ float g_part[64*D];

// ---------------- pack adjacency into bitmask ----------------
__global__ void pack_kernel(const int* __restrict__ adj,
                            unsigned int* __restrict__ bits) {
    unsigned int g = blockIdx.x * blockDim.x + threadIdx.x;
    unsigned int b = __ballot_sync(0xffffffffu, adj[g] != 0);
    if ((g & 31u) == 0u) bits[g >> 5] = b;
}

// ---------------- generic tiled fp32 GEMM: C = act(A@B + bias) ----------------
// BM=BN=64, BK=32, 256 threads, 4x4 microtile. grid = (M/64, N_out/64)
__global__ __launch_bounds__(256) void gemm_kernel(
    const float* __restrict__ A, int lda,
    const float* __restrict__ B, int ldb,
    const float* __restrict__ bias,
    float* __restrict__ C, int ldc,
    int K, int act) {
    __shared__ float As[32][68];
    __shared__ float Bs[32][68];
    int tid = threadIdx.x;
    int m0 = blockIdx.x * 64;
    int n0 = blockIdx.y * 64;
    int tx = tid & 15, ty = tid >> 4;
    float acc[4][4];
#pragma unroll
    for (int r = 0; r < 4; r++)
#pragma unroll
        for (int c = 0; c < 4; c++) acc[r][c] = 0.f;

    for (int kb = 0; kb < K; kb += 32) {
#pragma unroll
        for (int i = 0; i < 8; i++) {
            int lin = tid + i * 256;
            int k = lin & 31, m = lin >> 5;
            As[k][m] = A[(size_t)(m0 + m) * lda + kb + k];
        }
#pragma unroll
        for (int i = 0; i < 8; i++) {
            int lin = tid + i * 256;
            int n = lin & 63, k = lin >> 6;
            Bs[k][n] = B[(size_t)(kb + k) * ldb + n0 + n];
        }
        __syncthreads();
#pragma unroll
        for (int kk = 0; kk < 32; kk++) {
            float4 av = *(const float4*)&As[kk][ty * 4];
            float4 bv = *(const float4*)&Bs[kk][tx * 4];
            float a_[4] = {av.x, av.y, av.z, av.w};
            float b_[4] = {bv.x, bv.y, bv.z, bv.w};
#pragma unroll
            for (int r = 0; r < 4; r++)
#pragma unroll
                for (int c = 0; c < 4; c++)
                    acc[r][c] = fmaf(a_[r], b_[c], acc[r][c]);
        }
        __syncthreads();
    }
    float4 bv = make_float4(0.f, 0.f, 0.f, 0.f);
    if (bias) bv = *(const float4*)&bias[n0 + tx * 4];
#pragma unroll
    for (int r = 0; r < 4; r++) {
        float4 o;
        o.x = acc[r][0] + bv.x; o.y = acc[r][1] + bv.y;
        o.z = acc[r][2] + bv.z; o.w = acc[r][3] + bv.w;
        if (act == 1) {
            o.x = fmaxf(o.x, 0.f); o.y = fmaxf(o.y, 0.f);
            o.z = fmaxf(o.z, 0.f); o.w = fmaxf(o.w, 0.f);
        }
        *(float4*)&C[(size_t)(m0 + ty * 4 + r) * ldc + n0 + tx * 4] = o;
    }
}

// ---------------- f1/f2 projections: f1[i]=Wh[i]·a[:128], f2[i]=Wh[i]·a[128:] ----------------
__global__ void fvec_kernel(const float* __restrict__ Wh,
                            const float* __restrict__ avec,
                            float* __restrict__ f1, float* __restrict__ f2) {
    int i = blockIdx.x, t = threadIdx.x;   // 128 threads
    float w = Wh[(size_t)i * D + t];
    float v1 = w * avec[t];
    float v2 = w * avec[128 + t];
#pragma unroll
    for (int o = 16; o > 0; o >>= 1) {
        v1 += __shfl_down_sync(0xffffffffu, v1, o);
        v2 += __shfl_down_sync(0xffffffffu, v2, o);
    }
    __shared__ float s1[4], s2[4];
    if ((t & 31) == 0) { s1[t >> 5] = v1; s2[t >> 5] = v2; }
    __syncthreads();
    if (t == 0) {
        f1[i] = s1[0] + s1[1] + s1[2] + s1[3];
        f2[i] = s2[0] + s2[1] + s2[2] + s2[3];
    }
}

// ---------------- fused masked-softmax attention (flash style) ----------------
// 128 threads, R=16 rows/CTA, chunk of CK=128 columns. gridDim.y = heads.
// out[i][off + :] = elu( softmax_j(mask? lrelu(f1_i+f2_j): -9e15) @ V )
__global__ __launch_bounds__(128) void att_kernel(
    const unsigned int* __restrict__ bits,
    const float* __restrict__ f1b_, const float* __restrict__ f2b_,
    const float* __restrict__ Vb_,
    float* __restrict__ out, int out_ld, int head_off) {
    extern __shared__ float smem[];
    float* Vs = smem;            // CK*D
    float* es = smem + CK * D;   // R*CK (e, then p)
    __shared__ float sm_m[R], sm_alpha[R], sm_l[R], sm_f1[R];

    int head = blockIdx.y;
    const float* f1 = f1b_ + (size_t)head * NN;
    const float* f2 = f2b_ + (size_t)head * NN;
    const float* V = Vb_ + (size_t)head * NN * D;
    int off = head * head_off;

    int tid = threadIdx.x;
    int warp = tid >> 5, lane = tid & 31;
    int i0 = blockIdx.x * R;
    int myrow0 = warp * 4;
    int fc = lane * 4;

    if (tid < R) { sm_m[tid] = -INFINITY; sm_l[tid] = 0.f; sm_f1[tid] = f1[i0 + tid]; }
    float acc[4][4];
#pragma unroll
    for (int r = 0; r < 4; r++)
#pragma unroll
        for (int c = 0; c < 4; c++) acc[r][c] = 0.f;
    __syncthreads();

    for (int j0 = 0; j0 < NN; j0 += CK) {
        // stage V tile (CK x D) -> smem, fully coalesced float4
        const float4* Vg = (const float4*)(V + (size_t)j0 * D);
        float4* Vs4 = (float4*)Vs;
#pragma unroll
        for (int k = 0; k < (CK * D / 4) / 128; k++)
            Vs4[tid + k * 128] = Vg[tid + k * 128];

        // e for (row r, col j0+tid)
        float f2j = f2[j0 + tid];
        int wbase = i0 * WORDS + (j0 >> 5) + (tid >> 5);
#pragma unroll
        for (int r = 0; r < R; r++) {
            unsigned int w = bits[wbase + r * WORDS];
            float v = sm_f1[r] + f2j;
            float e = ((w >> (tid & 31)) & 1u) ? (v > 0.f ? v : 0.2f * v) : NEG_INF;
            es[r * CK + tid] = e;
        }
        __syncthreads();

        // per-row chunk max (warp w owns rows 4w..4w+3; 8 lanes per row)
        {
            int row = myrow0 + (lane >> 3);
            int sub = lane & 7;
            float mx = -INFINITY;
#pragma unroll
            for (int k = 0; k < CK / 8; k++) mx = fmaxf(mx, es[row * CK + sub + k * 8]);
            mx = fmaxf(mx, __shfl_xor_sync(0xffffffffu, mx, 4));
            mx = fmaxf(mx, __shfl_xor_sync(0xffffffffu, mx, 2));
            mx = fmaxf(mx, __shfl_xor_sync(0xffffffffu, mx, 1));
            if (sub == 0) {
                float mold = sm_m[row];
                float mnew = fmaxf(mold, mx);
                sm_alpha[row] = __expf(mold - mnew);   // 0 on first chunk
                sm_m[row] = mnew;
            }
        }
        __syncthreads();

        // p = exp(e - m)   (NEG_INF entries -> 0; all-masked row -> uniform, matches ref)
#pragma unroll
        for (int r = 0; r < R; r++) {
            float p = __expf(es[r * CK + tid] - sm_m[r]);
            es[r * CK + tid] = p;
        }
        __syncthreads();

        // per-row chunk sum -> l update
        {
            int row = myrow0 + (lane >> 3);
            int sub = lane & 7;
            float s = 0.f;
#pragma unroll
            for (int k = 0; k < CK / 8; k++) s += es[row * CK + sub + k * 8];
            s += __shfl_xor_sync(0xffffffffu, s, 4);
            s += __shfl_xor_sync(0xffffffffu, s, 2);
            s += __shfl_xor_sync(0xffffffffu, s, 1);
            if (sub == 0) sm_l[row] = sm_l[row] * sm_alpha[row] + s;
        }

        // rescale + accumulate: 16 FMA per (1 LDS.128 + 4 bcast LDS) -> FMA bound
#pragma unroll
        for (int r = 0; r < 4; r++) {
            float a = sm_alpha[myrow0 + r];
            acc[r][0] *= a; acc[r][1] *= a; acc[r][2] *= a; acc[r][3] *= a;
        }
#pragma unroll 4
        for (int j = 0; j < CK; j++) {
            float4 v = *(const float4*)(Vs + j * D + fc);
#pragma unroll
            for (int r = 0; r < 4; r++) {
                float p = es[(myrow0 + r) * CK + j];
                acc[r][0] = fmaf(p, v.x, acc[r][0]);
                acc[r][1] = fmaf(p, v.y, acc[r][1]);
                acc[r][2] = fmaf(p, v.z, acc[r][2]);
                acc[r][3] = fmaf(p, v.w, acc[r][3]);
            }
        }
        __syncthreads();
    }

    // epilogue: divide by l, elu, store
#pragma unroll
    for (int r = 0; r < 4; r++) {
        int row = i0 + myrow0 + r;
        float inv = 1.f / sm_l[myrow0 + r];
        float4 o;
        o.x = acc[r][0] * inv; o.y = acc[r][1] * inv;
        o.z = acc[r][2] * inv; o.w = acc[r][3] * inv;
        o.x = o.x > 0.f ? o.x : expm1f(o.x);
        o.y = o.y > 0.f ? o.y : expm1f(o.y);
        o.z = o.z > 0.f ? o.z : expm1f(o.z);
        o.w = o.w > 0.f ? o.w : expm1f(o.w);
        *(float4*)(out + (size_t)row * out_ld + off + fc) = o;
    }
}

// ---------------- combined = [x, node_emb] ----------------
__global__ void concat_kernel(const float* __restrict__ x,
                              const float* __restrict__ ne,
                              float* __restrict__ comb) {
    int idx = blockIdx.x * 256 + threadIdx.x;   // over NN*64 float4
    int row = idx >> 6, c = idx & 63;
    float4 v = (c < 32) ? ((const float4*)x)[(size_t)row * 32 + c]
                        : ((const float4*)ne)[(size_t)row * 32 + (c - 32)];
    ((float4*)comb)[idx] = v;
}

// ---------------- column mean over rows ----------------
__global__ void mean_part(const float* __restrict__ h2, float* __restrict__ part) {
    int b = blockIdx.x, t = threadIdx.x;   // 64 blocks x 128 threads
    float s = 0.f;
    for (int r = 0; r < 128; r++) s += h2[(size_t)(b * 128 + r) * D + t];
    part[b * D + t] = s;
}
__global__ void mean_final(const float* __restrict__ part, float* __restrict__ out) {
    int t = threadIdx.x;
    float s = 0.f;
    for (int b = 0; b < 64; b++) s += part[b * D + t];
    out[t] = s * (1.0f / (float)NN);
}

// ---------------- launch ----------------
extern "C" void kernel_launch(void* const* d_in, const int* in_sizes, int n_in,
                              void* d_out, int out_size) {
    const int* adj = (const int*)d_in[0];
    const float* x = (const float*)d_in[1];
    const float* W_heads = (const float*)d_in[2];
    const float* a_heads = (const float*)d_in[3];
    const float* W_out = (const float*)d_in[4];
    const float* a_out = (const float*)d_in[5];
    const float* ge_w1 = (const float*)d_in[6];
    const float* ge_b1 = (const float*)d_in[7];
    const float* ge_w2 = (const float*)d_in[8];
    const float* ge_b2 = (const float*)d_in[9];
    float* out = (float*)d_out;

    unsigned int* bits; cudaGetSymbolAddress((void**)&bits, g_bits);
    float* Wh;   cudaGetSymbolAddress((void**)&Wh, g_Wh);
    float* f1;   cudaGetSymbolAddress((void**)&f1, g_f1);
    float* f2;   cudaGetSymbolAddress((void**)&f2, g_f2);
    float* h;    cudaGetSymbolAddress((void**)&h, g_h);
    float* Wh2;  cudaGetSymbolAddress((void**)&Wh2, g_Wh2);
    float* f1o;  cudaGetSymbolAddress((void**)&f1o, g_f1o);
    float* f2o;  cudaGetSymbolAddress((void**)&f2o, g_f2o);
    float* comb; cudaGetSymbolAddress((void**)&comb, g_comb);
    float* mlp1; cudaGetSymbolAddress((void**)&mlp1, g_mlp1);
    float* mlp2; cudaGetSymbolAddress((void**)&mlp2, g_mlp2);
    float* part; cudaGetSymbolAddress((void**)&part, g_part);

    cudaFuncSetAttribute(att_kernel, cudaFuncAttributeMaxDynamicSharedMemorySize, ATT_SMEM);

    // 1. pack adjacency -> bits (256 MB read once)
    pack_kernel<<<NN * NN / 256, 256>>>(adj, bits);

    // 2. Wh per head = x @ W_heads[i]
    dim3 g128(NN / 64, 2);
    gemm_kernel<<<g128, 256>>>(x, D, W_heads, D, nullptr, Wh, D, D, 0);
    gemm_kernel<<<g128, 256>>>(x, D, W_heads + D * D, D, nullptr, Wh + NN * D, D, D, 0);

    // 3. f1/f2 per head
    fvec_kernel<<<NN, 128>>>(Wh, a_heads, f1, f2);
    fvec_kernel<<<NN, 128>>>(Wh + NN * D, a_heads + 256, f1 + NN, f2 + NN);

    // 4. layer-1 attention, both heads in one launch -> g_h (elu, concat)
    att_kernel<<<dim3(NN / R, 2), 128, ATT_SMEM>>>(bits, f1, f2, Wh, h, 256, 128);

    // 5. out-attention layer
    gemm_kernel<<<g128, 256>>>(h, 256, W_out, D, nullptr, Wh2, D, 256, 0);
    fvec_kernel<<<NN, 128>>>(Wh2, a_out, f1o, f2o);
    att_kernel<<<dim3(NN / R, 1), 128, ATT_SMEM>>>(bits, f1o, f2o, Wh2, out, D, 0);

    // 6. readout MLP + mean
    concat_kernel<<<NN * 256 / 4 / 256, 256>>>(x, out, comb);
    gemm_kernel<<<dim3(NN / 64, 4), 256>>>(comb, 256, ge_w1, 256, ge_b1, mlp1, 256, 256, 1);
    gemm_kernel<<<dim3(NN / 64, 2), 256>>>(mlp1, 256, ge_w2, D, ge_b2, mlp2, D, 256, 1);
    mean_part<<<64, 128>>>(mlp2, part);
    mean_final<<<1, 128>>>(part, out + (size_t)NN * D);
}

// round 2
// speedup vs baseline: 2.0250x; 2.0250x over previous
#include <cuda_runtime.h>
#include <math.h>
#include <stdint.h>

#define NN 8192
#define D 128
#define WORDS (NN/32)
#define M 64            // rows per attention CTA
#define CK 128          // j-chunk
#define PAD 140         // smem row pitch (conflict-free for mma frag loads)
#define ATT_SMEM ((CK + M) * PAD * 4)

// ---------------- device scratch ----------------
__device__ unsigned int g_bits[NN*WORDS];
__device__ float g_Wh[2*NN*D];
__device__ float g_Wht[2*NN*D];     // tf32-rounded V for layer 1
__device__ float g_f1[2*NN];
__device__ float g_f2[2*NN];
__device__ float g_m[2*NN];
__device__ float g_h[NN*256];
__device__ float g_Wh2[NN*D];
__device__ float g_Wh2t[NN*D];
__device__ float g_f1o[NN];
__device__ float g_f2o[NN];
__device__ float g_mo[NN];
__device__ float g_comb[NN*256];
__device__ float g_mlp1[NN*256];
__device__ float g_mlp2[NN*D];
__device__ float g_part[64*D];

__device__ __forceinline__ unsigned int f2tf32(float x) {
    unsigned int r;
    asm("cvt.rna.tf32.f32 %0, %1;" : "=r"(r) : "f"(x));
    return r;
}

// ---------------- pack adjacency into bitmask ----------------
__global__ void pack_kernel(const int* __restrict__ adj,
                            unsigned int* __restrict__ bits) {
    unsigned int g = blockIdx.x * blockDim.x + threadIdx.x;
    unsigned int b = __ballot_sync(0xffffffffu, adj[g] != 0);
    if ((g & 31u) == 0u) bits[g >> 5] = b;
}

// ---------------- tf32 rounding pass ----------------
__global__ void round_kernel(const float* __restrict__ in, float* __restrict__ out) {
    int i = blockIdx.x * 256 + threadIdx.x;
    out[i] = __uint_as_float(f2tf32(in[i]));
}

// ---------------- generic tiled fp32 GEMM: C = act(A@B + bias) ----------------
__global__ __launch_bounds__(256) void gemm_kernel(
    const float* __restrict__ A, int lda,
    const float* __restrict__ B, int ldb,
    const float* __restrict__ bias,
    float* __restrict__ C, int ldc,
    int K, int act) {
    __shared__ float As[32][68];
    __shared__ float Bs[32][68];
    int tid = threadIdx.x;
    int m0 = blockIdx.x * 64;
    int n0 = blockIdx.y * 64;
    int tx = tid & 15, ty = tid >> 4;
    float acc[4][4];
#pragma unroll
    for (int r = 0; r < 4; r++)
#pragma unroll
        for (int c = 0; c < 4; c++) acc[r][c] = 0.f;

    for (int kb = 0; kb < K; kb += 32) {
#pragma unroll
        for (int i = 0; i < 8; i++) {
            int lin = tid + i * 256;
            int k = lin & 31, m = lin >> 5;
            As[k][m] = A[(size_t)(m0 + m) * lda + kb + k];
        }
#pragma unroll
        for (int i = 0; i < 8; i++) {
            int lin = tid + i * 256;
            int n = lin & 63, k = lin >> 6;
            Bs[k][n] = B[(size_t)(kb + k) * ldb + n0 + n];
        }
        __syncthreads();
#pragma unroll
        for (int kk = 0; kk < 32; kk++) {
            float4 av = *(const float4*)&As[kk][ty * 4];
            float4 bv = *(const float4*)&Bs[kk][tx * 4];
            float a_[4] = {av.x, av.y, av.z, av.w};
            float b_[4] = {bv.x, bv.y, bv.z, bv.w};
#pragma unroll
            for (int r = 0; r < 4; r++)
#pragma unroll
                for (int c = 0; c < 4; c++)
                    acc[r][c] = fmaf(a_[r], b_[c], acc[r][c]);
        }
        __syncthreads();
    }
    float4 bv = make_float4(0.f, 0.f, 0.f, 0.f);
    if (bias) bv = *(const float4*)&bias[n0 + tx * 4];
#pragma unroll
    for (int r = 0; r < 4; r++) {
        float4 o;
        o.x = acc[r][0] + bv.x; o.y = acc[r][1] + bv.y;
        o.z = acc[r][2] + bv.z; o.w = acc[r][3] + bv.w;
        if (act == 1) {
            o.x = fmaxf(o.x, 0.f); o.y = fmaxf(o.y, 0.f);
            o.z = fmaxf(o.z, 0.f); o.w = fmaxf(o.w, 0.f);
        }
        *(float4*)&C[(size_t)(m0 + ty * 4 + r) * ldc + n0 + tx * 4] = o;
    }
}

// ---------------- f1/f2 projections ----------------
__global__ void fvec_kernel(const float* __restrict__ Wh,
                            const float* __restrict__ avec,
                            float* __restrict__ f1, float* __restrict__ f2) {
    int i = blockIdx.x, t = threadIdx.x;
    float w = Wh[(size_t)i * D + t];
    float v1 = w * avec[t];
    float v2 = w * avec[128 + t];
#pragma unroll
    for (int o = 16; o > 0; o >>= 1) {
        v1 += __shfl_down_sync(0xffffffffu, v1, o);
        v2 += __shfl_down_sync(0xffffffffu, v2, o);
    }
    __shared__ float s1[4], s2[4];
    if ((t & 31) == 0) { s1[t >> 5] = v1; s2[t >> 5] = v2; }
    __syncthreads();
    if (t == 0) {
        f1[i] = s1[0] + s1[1] + s1[2] + s1[3];
        f2[i] = s2[0] + s2[1] + s2[2] + s2[3];
    }
}

// ---------------- true row max: m_i = lrelu(f1_i + max_{j in N(i)} f2_j) ----------------
__global__ void rowmax_kernel(const unsigned int* __restrict__ bits,
                              const float* __restrict__ f1b,
                              const float* __restrict__ f2b,
                              float* __restrict__ mb) {
    int head = blockIdx.y;
    int i = blockIdx.x;
    int tid = threadIdx.x;                  // 128 threads
    const float* f2 = f2b + (size_t)head * NN;
    float mx = -INFINITY;
    int wb = i * WORDS + (tid >> 5);
    unsigned int bit = 1u << (tid & 31);
#pragma unroll 8
    for (int k = 0; k < 64; k++) {
        unsigned int w = bits[wb + k * 4];
        float v = f2[tid + k * 128];
        if (w & bit) mx = fmaxf(mx, v);
    }
#pragma unroll
    for (int o = 16; o > 0; o >>= 1)
        mx = fmaxf(mx, __shfl_xor_sync(0xffffffffu, mx, o));
    __shared__ float sm[4];
    if ((tid & 31) == 0) sm[tid >> 5] = mx;
    __syncthreads();
    if (tid == 0) {
        mx = fmaxf(fmaxf(sm[0], sm[1]), fmaxf(sm[2], sm[3]));
        float v = f1b[(size_t)head * NN + i] + mx;
        mb[(size_t)head * NN + i] = v > 0.f ? v : 0.2f * v;
    }
}

// ---------------- tf32 tensor-core masked-softmax attention ----------------
// 256 threads, M=64 rows/CTA, CK=128 j-chunks, warp (w>>1)->m16 quad, (w&1)->n64 half.
__global__ __launch_bounds__(256, 2) void att_mma(
    const unsigned int* __restrict__ bits,
    const float* __restrict__ f1b, const float* __restrict__ f2b,
    const float* __restrict__ mb,
    const float* __restrict__ Vb,
    float* __restrict__ out, int out_ld, int head_off) {
    extern __shared__ float smem[];
    float* Vs = smem;                 // [CK][PAD] (tf32 bits as float)
    float* Ps = smem + CK * PAD;      // [M][PAD]
    __shared__ float sm_f1[M], sm_m[M], sm_l[M];

    int head = blockIdx.y;
    const float* f1 = f1b + (size_t)head * NN;
    const float* f2 = f2b + (size_t)head * NN;
    const float* mrv = mb + (size_t)head * NN;
    const float* V = Vb + (size_t)head * NN * D;
    int off = head * head_off;

    int tid = threadIdx.x;
    int lane = tid & 31, warp = tid >> 5;
    int i0 = blockIdx.x * M;
    int mrow0 = (warp >> 1) * 16;
    int ncol0 = (warp & 1) * 64;

    if (tid < M) { sm_f1[tid] = f1[i0 + tid]; sm_m[tid] = mrv[i0 + tid]; }

    float acc[8][4];
#pragma unroll
    for (int nt = 0; nt < 8; nt++)
#pragma unroll
        for (int c = 0; c < 4; c++) acc[nt][c] = 0.f;
    float lsum = 0.f;

    int scol = tid & 127;          // score column within chunk
    int srbase = (tid >> 7) * 32;  // this thread handles rows srbase..srbase+31
    unsigned int sbit = 1u << (scol & 31);
    __syncthreads();

    for (int j0 = 0; j0 < NN; j0 += CK) {
        // ---- stage V chunk (pre-rounded tf32) into padded smem ----
        const float4* Vg = (const float4*)(V + (size_t)j0 * D);
#pragma unroll
        for (int it = 0; it < 16; it++) {
            int idx = tid + it * 256;      // 0..4095 float4
            int j = idx >> 5, c = idx & 31;
            float4 v = Vg[idx];
            *(float4*)(Vs + j * PAD + c * 4) = v;
        }
        // ---- scores -> p (tf32) ----
        float f2j = f2[j0 + scol];
        int wbase = (i0 + srbase) * WORDS + (j0 >> 5) + (scol >> 5);
#pragma unroll 8
        for (int r = 0; r < 32; r++) {
            unsigned int w = bits[wbase + r * WORDS];
            int row = srbase + r;
            float v = sm_f1[row] + f2j;
            v = v > 0.f ? v : 0.2f * v;
            float p = (w & sbit) ? __expf(v - sm_m[row]) : 0.f;
            Ps[row * PAD + scol] = __uint_as_float(f2tf32(p));
        }
        __syncthreads();

        // ---- l partial (thread owns row tid>>2, quarter tid&3) ----
        {
            const float* pr = Ps + (tid >> 2) * PAD + (tid & 3) * 32;
            float s = 0.f;
#pragma unroll
            for (int k = 0; k < 32; k++) s += pr[k];
            lsum += s;
        }
        // ---- tf32 mma: (m16 x k8) x (k8 x n8) x 8 ntiles x 16 ksteps ----
#pragma unroll
        for (int k = 0; k < 16; k++) {
            int ar = mrow0 + (lane >> 2);
            int ac = k * 8 + (lane & 3);
            uint32_t a0 = __float_as_uint(Ps[ar * PAD + ac]);
            uint32_t a1 = __float_as_uint(Ps[(ar + 8) * PAD + ac]);
            uint32_t a2 = __float_as_uint(Ps[ar * PAD + ac + 4]);
            uint32_t a3 = __float_as_uint(Ps[(ar + 8) * PAD + ac + 4]);
            int br = k * 8 + (lane & 3);
#pragma unroll
            for (int nt = 0; nt < 8; nt++) {
                int bc = ncol0 + nt * 8 + (lane >> 2);
                uint32_t b0 = __float_as_uint(Vs[br * PAD + bc]);
                uint32_t b1 = __float_as_uint(Vs[(br + 4) * PAD + bc]);
                asm volatile(
                    "mma.sync.aligned.m16n8k8.row.col.f32.tf32.tf32.f32 "
                    "{%0,%1,%2,%3},{%4,%5,%6,%7},{%8,%9},{%0,%1,%2,%3};"
                    : "+f"(acc[nt][0]), "+f"(acc[nt][1]),
                      "+f"(acc[nt][2]), "+f"(acc[nt][3])
                    : "r"(a0), "r"(a1), "r"(a2), "r"(a3), "r"(b0), "r"(b1));
            }
        }
        __syncthreads();
    }

    // ---- reduce l across the 4 quarters per row ----
    {
        float s = lsum;
        s += __shfl_xor_sync(0xffffffffu, s, 1);
        s += __shfl_xor_sync(0xffffffffu, s, 2);
        if ((lane & 3) == 0) sm_l[tid >> 2] = s;
    }
    __syncthreads();

    // ---- epilogue: /l, elu, store ----
    int r0 = mrow0 + (lane >> 2);
    float inv0 = 1.f / sm_l[r0];
    float inv1 = 1.f / sm_l[r0 + 8];
#pragma unroll
    for (int nt = 0; nt < 8; nt++) {
        int col = ncol0 + nt * 8 + (lane & 3) * 2;
        float2 o0, o1;
        o0.x = acc[nt][0] * inv0; o0.y = acc[nt][1] * inv0;
        o1.x = acc[nt][2] * inv1; o1.y = acc[nt][3] * inv1;
        o0.x = o0.x > 0.f ? o0.x : expm1f(o0.x);
        o0.y = o0.y > 0.f ? o0.y : expm1f(o0.y);
        o1.x = o1.x > 0.f ? o1.x : expm1f(o1.x);
        o1.y = o1.y > 0.f ? o1.y : expm1f(o1.y);
        *(float2*)(out + (size_t)(i0 + r0) * out_ld + off + col) = o0;
        *(float2*)(out + (size_t)(i0 + r0 + 8) * out_ld + off + col) = o1;
    }
}

// ---------------- combined = [x, node_emb] ----------------
__global__ void concat_kernel(const float* __restrict__ x,
                              const float* __restrict__ ne,
                              float* __restrict__ comb) {
    int idx = blockIdx.x * 256 + threadIdx.x;
    int row = idx >> 6, c = idx & 63;
    float4 v = (c < 32) ? ((const float4*)x)[(size_t)row * 32 + c]
                        : ((const float4*)ne)[(size_t)row * 32 + (c - 32)];
    ((float4*)comb)[idx] = v;
}

// ---------------- column mean over rows ----------------
__global__ void mean_part(const float* __restrict__ h2, float* __restrict__ part) {
    int b = blockIdx.x, t = threadIdx.x;
    float s = 0.f;
    for (int r = 0; r < 128; r++) s += h2[(size_t)(b * 128 + r) * D + t];
    part[b * D + t] = s;
}
__global__ void mean_final(const float* __restrict__ part, float* __restrict__ out) {
    int t = threadIdx.x;
    float s = 0.f;
    for (int b = 0; b < 64; b++) s += part[b * D + t];
    out[t] = s * (1.0f / (float)NN);
}

// ---------------- launch ----------------
extern "C" void kernel_launch(void* const* d_in, const int* in_sizes, int n_in,
                              void* d_out, int out_size) {
    const int* adj = (const int*)d_in[0];
    const float* x = (const float*)d_in[1];
    const float* W_heads = (const float*)d_in[2];
    const float* a_heads = (const float*)d_in[3];
    const float* W_out = (const float*)d_in[4];
    const float* a_out = (const float*)d_in[5];
    const float* ge_w1 = (const float*)d_in[6];
    const float* ge_b1 = (const float*)d_in[7];
    const float* ge_w2 = (const float*)d_in[8];
    const float* ge_b2 = (const float*)d_in[9];
    float* out = (float*)d_out;

    unsigned int* bits; cudaGetSymbolAddress((void**)&bits, g_bits);
    float* Wh;    cudaGetSymbolAddress((void**)&Wh, g_Wh);
    float* Wht;   cudaGetSymbolAddress((void**)&Wht, g_Wht);
    float* f1;    cudaGetSymbolAddress((void**)&f1, g_f1);
    float* f2;    cudaGetSymbolAddress((void**)&f2, g_f2);
    float* m;     cudaGetSymbolAddress((void**)&m, g_m);
    float* h;     cudaGetSymbolAddress((void**)&h, g_h);
    float* Wh2;   cudaGetSymbolAddress((void**)&Wh2, g_Wh2);
    float* Wh2t;  cudaGetSymbolAddress((void**)&Wh2t, g_Wh2t);
    float* f1o;   cudaGetSymbolAddress((void**)&f1o, g_f1o);
    float* f2o;   cudaGetSymbolAddress((void**)&f2o, g_f2o);
    float* mo;    cudaGetSymbolAddress((void**)&mo, g_mo);
    float* comb;  cudaGetSymbolAddress((void**)&comb, g_comb);
    float* mlp1;  cudaGetSymbolAddress((void**)&mlp1, g_mlp1);
    float* mlp2;  cudaGetSymbolAddress((void**)&mlp2, g_mlp2);
    float* part;  cudaGetSymbolAddress((void**)&part, g_part);

    cudaFuncSetAttribute(att_mma, cudaFuncAttributeMaxDynamicSharedMemorySize, ATT_SMEM);

    // 1. pack adjacency
    pack_kernel<<<NN * NN / 256, 256>>>(adj, bits);

    // 2. Wh per head + tf32 round
    dim3 g128(NN / 64, 2);
    gemm_kernel<<<g128, 256>>>(x, D, W_heads, D, nullptr, Wh, D, D, 0);
    gemm_kernel<<<g128, 256>>>(x, D, W_heads + D * D, D, nullptr, Wh + NN * D, D, D, 0);
    round_kernel<<<2 * NN * D / 256, 256>>>(Wh, Wht);

    // 3. f1/f2 + row maxima
    fvec_kernel<<<NN, 128>>>(Wh, a_heads, f1, f2);
    fvec_kernel<<<NN, 128>>>(Wh + NN * D, a_heads + 256, f1 + NN, f2 + NN);
    rowmax_kernel<<<dim3(NN, 2), 128>>>(bits, f1, f2, m);

    // 4. layer-1 attention (both heads), tensor cores
    att_mma<<<dim3(NN / M, 2), 256, ATT_SMEM>>>(bits, f1, f2, m, Wht, h, 256, 128);

    // 5. out-attention
    gemm_kernel<<<g128, 256>>>(h, 256, W_out, D, nullptr, Wh2, D, 256, 0);
    round_kernel<<<NN * D / 256, 256>>>(Wh2, Wh2t);
    fvec_kernel<<<NN, 128>>>(Wh2, a_out, f1o, f2o);
    rowmax_kernel<<<dim3(NN, 1), 128>>>(bits, f1o, f2o, mo);
    att_mma<<<dim3(NN / M, 1), 256, ATT_SMEM>>>(bits, f1o, f2o, mo, Wh2t, out, D, 0);

    // 6. readout MLP + mean
    concat_kernel<<<NN * 256 / 4 / 256, 256>>>(x, out, comb);
    gemm_kernel<<<dim3(NN / 64, 4), 256>>>(comb, 256, ge_w1, 256, ge_b1, mlp1, 256, 256, 1);
    gemm_kernel<<<dim3(NN / 64, 2), 256>>>(mlp1, 256, ge_w2, D, ge_b2, mlp2, D, 256, 1);
    mean_part<<<64, 128>>>(mlp2, part);
    mean_final<<<1, 128>>>(part, out + (size_t)NN * D);
}